// round 2
// baseline (speedup 1.0000x reference)
#include <cuda_runtime.h>

#define N_ANCH 262144
#define N_CLS 80
#define KTOP 1024
#define CAP 4096
#define NBLK 128
#define NTHR 256
#define FULLM 0xffffffffu

// ---------------- device scratch ----------------
__device__ unsigned            g_key[N_ANCH];
__device__ unsigned char       g_label[N_ANCH];
__device__ unsigned            g_hist[3][2048];
__device__ unsigned            g_barcnt;
__device__ unsigned            g_ncand;
__device__ unsigned            g_maxc;
__device__ unsigned long long  g_cand[CAP];
__device__ unsigned long long  g_sorted[KTOP];
__device__ float4              g_box[KTOP];
__device__ float               g_conf[KTOP];
__device__ float               g_labf[KTOP];
__device__ unsigned            g_mask[KTOP * 32];
__device__ unsigned char       g_rownz[KTOP];

__device__ __forceinline__ unsigned fkey(float f) {
    unsigned u = __float_as_uint(f);
    return (u & 0x80000000u) ? ~u : (u | 0x80000000u);
}

// ---------------- kernel 1: per-anchor max/argmax over 80 classes ----------------
__global__ void conf_kernel(const float* __restrict__ scores) {
    int tid = threadIdx.x;
    if (blockIdx.x == 0) {   // per-launch scratch reset (graph replays!)
        for (int i = tid; i < 3 * 2048; i += blockDim.x) ((unsigned*)g_hist)[i] = 0u;
        if (tid == 0) { g_barcnt = 0u; g_ncand = 0u; g_maxc = 0u; }
    }
    int lane = tid & 31;
    int n = (int)((blockIdx.x * blockDim.x + tid) >> 5);
    if (n >= N_ANCH) return;
    const float* p = scores + (size_t)n * N_CLS;
    unsigned b0 = __float_as_uint(p[lane]);
    unsigned b1 = __float_as_uint(p[lane + 32]);
    unsigned b2 = (lane < 16) ? __float_as_uint(p[64 + lane]) : 0u;
    unsigned loc = max(b0, max(b1, b2));
    unsigned vmax = __reduce_max_sync(FULLM, loc);
    unsigned m0 = __ballot_sync(FULLM, b0 == vmax);
    int label;
    if (m0) label = __ffs(m0) - 1;
    else {
        unsigned m1 = __ballot_sync(FULLM, b1 == vmax);
        if (m1) label = 32 + __ffs(m1) - 1;
        else {
            unsigned m2 = __ballot_sync(FULLM, (lane < 16) && (b2 == vmax));
            label = 64 + __ffs(m2) - 1;
        }
    }
    if (lane == 0) {
        float conf = __uint_as_float(vmax);
        float mk = (conf >= 0.5f) ? conf : -1.0f;
        g_key[n] = fkey(mk);
        g_label[n] = (unsigned char)label;
    }
}

// ---------------- grid spin-barrier (all NBLK blocks co-resident) ----------------
__device__ __forceinline__ void gridbar(unsigned epoch) {
    __threadfence();                 // publish this thread's prior writes
    __syncthreads();                 // all threads' fences done
    if (threadIdx.x == 0) {
        atomicAdd(&g_barcnt, 1u);
        while (atomicAdd(&g_barcnt, 0u) < epoch * (unsigned)NBLK) __nanosleep(64);
    }
    __syncthreads();
}

union SharedU {
    struct { unsigned sa[2048]; unsigned sb[2048]; } h;
    unsigned long long cbuf[1024];
    float4 sobox[1024];
};

// ---------------- kernel 2: everything else, fused (128 blocks x 256) ----------------
__global__ void __launch_bounds__(NTHR) mega_kernel(const float* __restrict__ boxes,
                                                    float* __restrict__ out) {
    __shared__ SharedU su;
    __shared__ unsigned s_sel, s_need;
    __shared__ unsigned keepw[32], nzm[32];
    __shared__ unsigned short list[1024];
    __shared__ int Lsh;

    const int tid  = threadIdx.x;
    const int lane = tid & 31;
    const int warp = tid >> 5;
    const int bid  = blockIdx.x;

    unsigned need = KTOP;
    unsigned sel1 = 0, sel2 = 0, thresh = 0;
    unsigned epoch = 0;

    // ===== 3 radix passes: warp-aggregated hist -> barrier -> redundant scan =====
#pragma unroll 1
    for (int pass = 0; pass < 3; pass++) {
        for (int i = tid; i < 2048; i += NTHR) su.h.sa[i] = 0u;
        __syncthreads();
#pragma unroll 1
        for (int n = bid * NTHR + tid; n < N_ANCH; n += NBLK * NTHR) {
            unsigned k = g_key[n];
            bool act; unsigned d;
            if (pass == 0)      { act = true;                                  d = k >> 21; }
            else if (pass == 1) { act = ((k >> 21) == sel1);                   d = (k >> 10) & 2047u; }
            else                { act = ((k >> 10) == ((sel1 << 11) | sel2));  d = k & 1023u; }
            unsigned am = __ballot_sync(FULLM, act);
            if (act) {
                unsigned peers = __match_any_sync(am, d);
                if ((__ffs(peers) - 1) == lane) atomicAdd(&su.h.sa[d], __popc(peers));
            }
        }
        __syncthreads();
        for (int i = tid; i < 2048; i += NTHR)
            if (su.h.sa[i]) atomicAdd(&g_hist[pass][i], su.h.sa[i]);
        gridbar(++epoch);

        // redundant per-block suffix-sum scan
        int NB = (pass == 2) ? 1024 : 2048;
        for (int i = tid; i < 2048; i += NTHR)
            su.h.sa[i] = (i < NB) ? __ldcg(&g_hist[pass][i]) : 0u;
        __syncthreads();
        unsigned* a = su.h.sa; unsigned* b = su.h.sb;
        for (int off = 1; off < 2048; off <<= 1) {
            for (int i = tid; i < 2048; i += NTHR)
                b[i] = a[i] + ((i + off < 2048) ? a[i + off] : 0u);
            __syncthreads();
            unsigned* t = a; a = b; b = t;
        }
        for (int i = tid; i < NB; i += NTHR) {
            unsigned Sincl = a[i];
            unsigned Sx = (i + 1 < 2048) ? a[i + 1] : 0u;
            if (Sx < need && need <= Sincl) { s_sel = (unsigned)i; s_need = need - Sx; }
        }
        __syncthreads();
        need = s_need;
        if (pass == 0)      sel1 = s_sel;
        else if (pass == 1) sel2 = s_sel;
        else                thresh = (sel1 << 21) | (sel2 << 10) | s_sel;
        __syncthreads();
    }

    // ===== compact candidates (key >= thresh) =====
    for (int n = bid * NTHR + tid; n < N_ANCH; n += NBLK * NTHR) {
        unsigned k = g_key[n];
        if (k >= thresh) {
            unsigned pos = atomicAdd(&g_ncand, 1u);
            if (pos < CAP)
                g_cand[pos] = (((unsigned long long)k) << 32) | (unsigned)(~(unsigned)n);
        }
    }
    gridbar(++epoch);

    // ===== rank by brute force (unique keys -> exact permutation) =====
    {
        unsigned nc = atomicAdd(&g_ncand, 0u);
        if (nc > CAP) nc = CAP;
        int i = bid * NTHR + tid;
        if ((unsigned)(bid * NTHR) < nc) {
            unsigned long long my = (i < (int)nc) ? __ldcg(&g_cand[i]) : 0ull;
            unsigned r = 0;
            for (unsigned base = 0; base < nc; base += 1024u) {
                unsigned len = min(1024u, nc - base);
                __syncthreads();
                for (unsigned j = tid; j < len; j += NTHR) su.cbuf[j] = __ldcg(&g_cand[base + j]);
                __syncthreads();
                if (i < (int)nc)
                    for (unsigned j = 0; j < len; j++) r += (su.cbuf[j] > my) ? 1u : 0u;
            }
            if (i < (int)nc && r < KTOP) g_sorted[r] = my;
        }
    }
    gridbar(++epoch);

    // ===== prep: gather boxes, global max coord =====
    if (tid < 8) {
        int r = bid * 8 + tid;
        unsigned long long s = __ldcg(&g_sorted[r]);
        unsigned idx = ~(unsigned)(s & 0xffffffffull);
        unsigned key = (unsigned)(s >> 32);
        unsigned fb = (key & 0x80000000u) ? (key & 0x7fffffffu) : ~key;
        float conf = __uint_as_float(fb);
        float4 bx = __ldg((const float4*)boxes + idx);
        unsigned lab = (unsigned)g_label[idx];
        g_box[r] = bx;
        g_conf[r] = conf;
        g_labf[r] = (float)lab;
        float m = fmaxf(fmaxf(bx.x, bx.y), fmaxf(bx.z, bx.w));
        atomicMax(&g_maxc, __float_as_uint(m));   // coords >= 0 -> monotone bits
    }
    gridbar(++epoch);

    // ===== mask: stage offset boxes in shared, 8 rows/block =====
    {
        float mc = __uint_as_float(__ldcg(&g_maxc)) + 1.0f;   // max(top_boxes)+1
        for (int j = tid; j < KTOP; j += NTHR) {
            float4 b = __ldcg(&g_box[j]);
            float off = __ldcg(&g_labf[j]) * mc;
            su.sobox[j] = make_float4(b.x + off, b.y + off, b.z + off, b.w + off);
        }
        __syncthreads();
        int row = bid * 8 + warp;
        float4 bi = su.sobox[row];
        float ai = (bi.z - bi.x) * (bi.w - bi.y);
        unsigned rowor = 0;
#pragma unroll 4
        for (int it = 0; it < 32; it++) {
            int j = it * 32 + lane;
            float4 bj = su.sobox[j];
            float aj = (bj.z - bj.x) * (bj.w - bj.y);
            float lx = fmaxf(bi.x, bj.x), ly = fmaxf(bi.y, bj.y);
            float rx = fminf(bi.z, bj.z), ry = fminf(bi.w, bj.w);
            float w = fmaxf(rx - lx, 0.0f), h = fmaxf(ry - ly, 0.0f);
            float inter = w * h;
            float uni = ai + aj - inter;
            float iou = inter / fmaxf(uni, 1e-9f);
            bool sup = (iou > 0.6f) && (j > row);
            unsigned bal = __ballot_sync(FULLM, sup);
            if (lane == 0) g_mask[row * 32 + it] = bal;
            rowor |= bal;
        }
        if (lane == 0) g_rownz[row] = (rowor != 0u) ? 1 : 0;
    }
    gridbar(++epoch);

    // ===== final: sparse greedy NMS + masked output (block 0 only) =====
    if (bid != 0) return;

    for (int w = warp; w < 32; w += 8) {
        float c = __ldcg(&g_conf[w * 32 + lane]);
        unsigned b = __ballot_sync(FULLM, c >= 0.5f);
        if (lane == 0) keepw[w] = b;
    }
    for (int w = warp; w < 32; w += 8) {
        unsigned char z = __ldcg(&g_rownz[w * 32 + lane]);
        unsigned b = __ballot_sync(FULLM, z != 0);
        if (lane == 0) nzm[w] = b;
    }
    __syncthreads();
    if (tid == 0) {
        int L = 0;
        for (int w = 0; w < 32; w++) {
            unsigned m = nzm[w];
            while (m) { int b = __ffs(m) - 1; list[L++] = (unsigned short)(w * 32 + b); m &= m - 1; }
        }
        Lsh = L;
    }
    __syncthreads();
    if (warp == 0) {
        unsigned kw = keepw[lane];
        int L = Lsh;
        for (int t = 0; t < L; t++) {
            int i = list[t];
            unsigned ow = __shfl_sync(FULLM, kw, i >> 5);
            if ((ow >> (i & 31)) & 1u) kw &= ~__ldcg(&g_mask[i * 32 + lane]);
        }
        keepw[lane] = kw;
    }
    __syncthreads();
    for (int r = tid; r < KTOP; r += NTHR) {
        bool kp = (keepw[r >> 5] >> (r & 31)) & 1u;
        float4 b = __ldcg(&g_box[r]);
        float c = __ldcg(&g_conf[r]);
        float lf = __ldcg(&g_labf[r]);
        float* o = out + r * 6;
        if (kp) { o[0] = b.x; o[1] = b.y; o[2] = b.z; o[3] = b.w; o[4] = c; o[5] = lf; }
        else    { o[0] = 0.f; o[1] = 0.f; o[2] = 0.f; o[3] = 0.f; o[4] = 0.f; o[5] = 0.f; }
    }
}

// ---------------- launch ----------------
extern "C" void kernel_launch(void* const* d_in, const int* in_sizes, int n_in,
                              void* d_out, int out_size) {
    const float* boxes  = (const float*)d_in[0];
    const float* scores = (const float*)d_in[1];
    if (n_in >= 2 && in_sizes[0] > in_sizes[1]) { const float* t = boxes; boxes = scores; scores = t; }

    conf_kernel<<<N_ANCH / 8, 256>>>(scores);
    mega_kernel<<<NBLK, NTHR>>>(boxes, (float*)d_out);
}

// round 3
// speedup vs baseline: 1.4463x; 1.4463x over previous
#include <cuda_runtime.h>

#define N_ANCH 262144
#define N_CLS 80
#define KTOP 1024
#define CAP 4096
#define FULLM 0xffffffffu

// ---------------- device scratch (zero-initialized at load; reset-at-end-of-use) ----
__device__ __align__(16) unsigned g_key[N_ANCH];
__device__ unsigned char       g_label[N_ANCH];
__device__ unsigned            g_hist0[2048], g_hist1[2048], g_hist2[1024];
__device__ unsigned            g_done0, g_done1, g_done2, g_done3, g_done4;
__device__ unsigned            g_sel1, g_sel2, g_need1, g_need2, g_thresh;
__device__ unsigned            g_ncand, g_maxc;
__device__ unsigned long long  g_cand[CAP];
__device__ unsigned long long  g_sorted[KTOP];
__device__ float4              g_box[KTOP];
__device__ float               g_conf[KTOP], g_labf[KTOP];
__device__ unsigned            g_mask[KTOP * 32];
__device__ unsigned char       g_rownz[KTOP];

__device__ __forceinline__ unsigned fkey(float f) {
    unsigned u = __float_as_uint(f);
    return (u & 0x80000000u) ? ~u : (u | 0x80000000u);
}

// Suffix-scan a histogram (256 threads), find the unique bin where the
// suffix-count crosses `need`; winner thread writes the pass result.
__device__ __forceinline__ void scan_pick(const unsigned* hist, int NB, unsigned need,
                                          unsigned* cA, unsigned* cB, int pass,
                                          unsigned sel1, unsigned sel2) {
    int tid = threadIdx.x;                 // 256 threads, 8 bins each
    unsigned v[8]; unsigned s = 0;
#pragma unroll
    for (int k = 0; k < 8; k++) { int i = tid * 8 + k; v[k] = (i < NB) ? __ldcg(&hist[i]) : 0u; s += v[k]; }
    cA[tid] = s;
    __syncthreads();
    unsigned* a = cA; unsigned* b = cB;
    for (int off = 1; off < 256; off <<= 1) {          // inclusive suffix over chunks
        unsigned x = a[tid] + ((tid + off < 256) ? a[tid + off] : 0u);
        b[tid] = x;
        __syncthreads();
        unsigned* t = a; a = b; b = t;
    }
    unsigned Cexcl = (tid + 1 < 256) ? a[tid + 1] : 0u;
    unsigned Sincl[8];
    unsigned run = Cexcl;
    for (int k = 7; k >= 0; k--) { run += v[k]; Sincl[k] = run; }
#pragma unroll
    for (int k = 0; k < 8; k++) {
        unsigned Sx = (k < 7) ? Sincl[k + 1] : Cexcl;  // strictly-above count
        if (Sx < need && need <= Sincl[k]) {
            unsigned bin = (unsigned)(tid * 8 + k);
            if (pass == 0)      { g_sel1 = bin; g_need1 = need - Sx; }
            else if (pass == 1) { g_sel2 = bin; g_need2 = need - Sx; }
            else                { g_thresh = (sel1 << 21) | (sel2 << 10) | bin; }
        }
    }
}

// ---------------- kernel 1: conf/argmax + fused hist pass 0 ----------------
// 4 lanes per anchor, 8 anchors per warp; 5x LDG.128 per thread.
__global__ void __launch_bounds__(256) conf_kernel(const float* __restrict__ scores) {
    __shared__ unsigned sh[2048];
    __shared__ unsigned cA[256], cB[256];
    __shared__ int lastFlag;
    int tid = threadIdx.x, lane = tid & 31;
    for (int i = tid; i < 2048; i += 256) sh[i] = 0u;

    int gw = (int)((blockIdx.x * 256u + tid) >> 5);
    int g = lane >> 2, c = lane & 3;
    int anchor = gw * 8 + g;
    const float4* p = (const float4*)scores + (size_t)anchor * 20;
    float4 f0 = __ldg(p + c);
    float4 f1 = __ldg(p + c + 4);
    float4 f2 = __ldg(p + c + 8);
    float4 f3 = __ldg(p + c + 12);
    float4 f4 = __ldg(p + c + 16);

    unsigned long long best = 0ull;
#define UPD(val, idx) { unsigned long long k64 = ((unsigned long long)__float_as_uint(val) << 32) \
                                               | (unsigned)(~(unsigned)(idx)); if (k64 > best) best = k64; }
    int b0 = 4 * c;
    UPD(f0.x, b0 + 0)  UPD(f0.y, b0 + 1)  UPD(f0.z, b0 + 2)  UPD(f0.w, b0 + 3)
    UPD(f1.x, b0 + 16) UPD(f1.y, b0 + 17) UPD(f1.z, b0 + 18) UPD(f1.w, b0 + 19)
    UPD(f2.x, b0 + 32) UPD(f2.y, b0 + 33) UPD(f2.z, b0 + 34) UPD(f2.w, b0 + 35)
    UPD(f3.x, b0 + 48) UPD(f3.y, b0 + 49) UPD(f3.z, b0 + 50) UPD(f3.w, b0 + 51)
    UPD(f4.x, b0 + 64) UPD(f4.y, b0 + 65) UPD(f4.z, b0 + 66) UPD(f4.w, b0 + 67)
#undef UPD
    // reduce over the 4 lanes of this anchor (tie -> lower class idx, = jnp.argmax)
    unsigned long long o;
    o = __shfl_xor_sync(FULLM, best, 1); if (o > best) best = o;
    o = __shfl_xor_sync(FULLM, best, 2); if (o > best) best = o;

    unsigned key = 0;
    bool act = (c == 0);
    if (act) {
        unsigned bits = (unsigned)(best >> 32);
        unsigned label = ~(unsigned)(best & 0xffffffffull);
        float conf = __uint_as_float(bits);
        float mk = (conf >= 0.5f) ? conf : -1.0f;
        key = fkey(mk);
        g_key[anchor] = key;
        g_label[anchor] = (unsigned char)label;
    }
    // warp-aggregated hist pass 0
    unsigned am = __ballot_sync(FULLM, act);
    if (act) {
        unsigned d = key >> 21;
        unsigned peers = __match_any_sync(am, d);
        if ((unsigned)(__ffs(peers) - 1) == (unsigned)lane) atomicAdd(&sh[d], __popc(peers));
    }
    __syncthreads();
    for (int i = tid; i < 2048; i += 256)
        if (sh[i]) atomicAdd(&g_hist0[i], sh[i]);
    __threadfence();
    if (tid == 0) lastFlag = (atomicAdd(&g_done0, 1u) == gridDim.x - 1);
    __syncthreads();
    if (!lastFlag) return;

    scan_pick(g_hist0, 2048, KTOP, cA, cB, 0, 0, 0);
    __syncthreads();
    for (int i = tid; i < 2048; i += 256) g_hist0[i] = 0u;   // reset for next replay
    if (tid == 0) g_done0 = 0u;
}

// ---------------- kernel 2/3: radix passes 1 and 2 (warp-agg + last-block scan) ----
__global__ void __launch_bounds__(256) hist_kernel(int pass) {
    __shared__ unsigned sh[2048];
    __shared__ unsigned cA[256], cB[256];
    __shared__ int lastFlag;
    int tid = threadIdx.x, lane = tid & 31;
    for (int i = tid; i < 2048; i += 256) sh[i] = 0u;
    unsigned sel1 = g_sel1;
    unsigned sel2 = (pass == 2) ? g_sel2 : 0u;
    unsigned pre = (sel1 << 11) | sel2;
    __syncthreads();

    int base = (int)(blockIdx.x * 256u + tid) * 4;
    uint4 kv = *(const uint4*)&g_key[base];
    unsigned ks[4] = {kv.x, kv.y, kv.z, kv.w};
#pragma unroll
    for (int e = 0; e < 4; e++) {
        unsigned k = ks[e];
        bool act; unsigned d;
        if (pass == 1) { act = ((k >> 21) == sel1); d = (k >> 10) & 2047u; }
        else           { act = ((k >> 10) == pre);  d = k & 1023u; }
        unsigned am = __ballot_sync(FULLM, act);
        if (act) {
            unsigned peers = __match_any_sync(am, d);
            if ((unsigned)(__ffs(peers) - 1) == (unsigned)lane) atomicAdd(&sh[d], __popc(peers));
        }
    }
    __syncthreads();
    unsigned* gh = (pass == 1) ? g_hist1 : g_hist2;
    int NB = (pass == 1) ? 2048 : 1024;
    for (int i = tid; i < NB; i += 256)
        if (sh[i]) atomicAdd(&gh[i], sh[i]);
    __threadfence();
    unsigned* dc = (pass == 1) ? &g_done1 : &g_done2;
    if (tid == 0) lastFlag = (atomicAdd(dc, 1u) == gridDim.x - 1);
    __syncthreads();
    if (!lastFlag) return;

    scan_pick(gh, NB, (pass == 1) ? g_need1 : g_need2, cA, cB, pass, sel1, sel2);
    __syncthreads();
    for (int i = tid; i < NB; i += 256) gh[i] = 0u;
    if (tid == 0) *dc = 0u;
}

// ---------------- kernel 4: compact candidates (warp-aggregated alloc) -----------
__global__ void __launch_bounds__(256) compact_kernel() {
    unsigned T = g_thresh;
    int lane = threadIdx.x & 31;
    int base = (int)(blockIdx.x * 256u + threadIdx.x) * 4;
    uint4 kv = *(const uint4*)&g_key[base];
    unsigned ks[4] = {kv.x, kv.y, kv.z, kv.w};
#pragma unroll
    for (int e = 0; e < 4; e++) {
        unsigned k = ks[e];
        bool sel = (k >= T);
        unsigned m = __ballot_sync(FULLM, sel);
        if (!m) continue;
        unsigned pos0;
        if (lane == 0) pos0 = atomicAdd(&g_ncand, __popc(m));
        pos0 = __shfl_sync(FULLM, pos0, 0);
        if (sel) {
            unsigned pos = pos0 + __popc(m & ((1u << lane) - 1u));
            if (pos < CAP)
                g_cand[pos] = (((unsigned long long)k) << 32) | (unsigned)(~(unsigned)(base + e));
        }
    }
}

// ---------------- kernel 5: rank (brute force) + prep fused in last block --------
__global__ void __launch_bounds__(1024) rank_kernel(const float* __restrict__ boxes) {
    __shared__ unsigned long long buf[CAP];     // 32 KB
    __shared__ int lastFlag;
    int tid = threadIdx.x;
    unsigned nc = __ldcg(&g_ncand);
    if (nc > CAP) nc = CAP;
    int i = (int)(blockIdx.x * 1024u) + tid;

    if (blockIdx.x * 1024u < nc) {
        for (unsigned j = tid; j < nc; j += 1024u) buf[j] = __ldcg(&g_cand[j]);
        __syncthreads();
        if (i < (int)nc) {
            unsigned long long my = buf[i];
            unsigned r = 0;
            for (unsigned j = 0; j < nc; j++) r += (buf[j] > my) ? 1u : 0u;
            if (r < KTOP) g_sorted[r] = my;
        }
    }
    __threadfence();
    if (tid == 0) lastFlag = (atomicAdd(&g_done3, 1u) == gridDim.x - 1);
    __syncthreads();
    if (!lastFlag) return;

    // ===== prep: decode sorted list, gather boxes, global max coordinate =====
    {
        int r = tid;  // 1024 threads, 1024 rows
        unsigned long long s = __ldcg(&g_sorted[r]);
        unsigned idx = ~(unsigned)(s & 0xffffffffull);
        unsigned kb = (unsigned)(s >> 32);
        unsigned fb = (kb & 0x80000000u) ? (kb & 0x7fffffffu) : ~kb;
        float4 bx = __ldg((const float4*)boxes + idx);
        g_box[r] = bx;
        g_conf[r] = __uint_as_float(fb);
        g_labf[r] = (float)(unsigned)g_label[idx];
        float m = fmaxf(fmaxf(bx.x, bx.y), fmaxf(bx.z, bx.w));
        atomicMax(&g_maxc, __float_as_uint(m));   // coords >= 0 -> bit-monotone
    }
    if (tid == 0) { g_done3 = 0u; g_ncand = 0u; }
}

// ---------------- kernel 6: IoU suppression mask + final NMS in last block -------
__global__ void __launch_bounds__(256) mask_kernel(float* __restrict__ out) {
    __shared__ float4 sobox[KTOP];              // 16 KB
    __shared__ int lastFlag;
    __shared__ unsigned keepw[32], nzm[32];
    __shared__ unsigned short list[KTOP];
    __shared__ int Lsh;
    int tid = threadIdx.x, lane = tid & 31, warp = tid >> 5;

    float mc = __uint_as_float(__ldcg(&g_maxc)) + 1.0f;   // max(top_boxes)+1
    for (int j = tid; j < KTOP; j += 256) {
        float4 b = __ldcg(&g_box[j]);
        float off = __ldcg(&g_labf[j]) * mc;
        sobox[j] = make_float4(b.x + off, b.y + off, b.z + off, b.w + off);
    }
    __syncthreads();

    int row = (int)blockIdx.x * 8 + warp;
    float4 bi = sobox[row];
    float ai = (bi.z - bi.x) * (bi.w - bi.y);
    unsigned rowor = 0;
#pragma unroll 4
    for (int it = 0; it < 32; it++) {
        int j = it * 32 + lane;
        float4 bj = sobox[j];
        float aj = (bj.z - bj.x) * (bj.w - bj.y);
        float lx = fmaxf(bi.x, bj.x), ly = fmaxf(bi.y, bj.y);
        float rx = fminf(bi.z, bj.z), ry = fminf(bi.w, bj.w);
        float w = fmaxf(rx - lx, 0.0f), h = fmaxf(ry - ly, 0.0f);
        float inter = w * h;
        float uni = ai + aj - inter;
        float iou = inter / fmaxf(uni, 1e-9f);
        bool sup = (iou > 0.6f) && (j > row);
        unsigned bal = __ballot_sync(FULLM, sup);
        if (lane == 0) g_mask[row * 32 + it] = bal;
        rowor |= bal;
    }
    if (lane == 0) g_rownz[row] = (rowor != 0u) ? 1 : 0;

    __threadfence();
    if (tid == 0) lastFlag = (atomicAdd(&g_done4, 1u) == gridDim.x - 1);
    __syncthreads();
    if (!lastFlag) return;

    // ===== final: sparse greedy NMS + masked output =====
    for (int w = warp; w < 32; w += 8) {
        float c = __ldcg(&g_conf[w * 32 + lane]);
        unsigned b = __ballot_sync(FULLM, c >= 0.5f);
        if (lane == 0) keepw[w] = b;
    }
    for (int w = warp; w < 32; w += 8) {
        unsigned char z = __ldcg(&g_rownz[w * 32 + lane]);
        unsigned b = __ballot_sync(FULLM, z != 0);
        if (lane == 0) nzm[w] = b;
    }
    __syncthreads();
    if (tid == 0) {
        int L = 0;
        for (int w = 0; w < 32; w++) {
            unsigned m = nzm[w];
            while (m) { int b = __ffs(m) - 1; list[L++] = (unsigned short)(w * 32 + b); m &= m - 1; }
        }
        Lsh = L;
    }
    __syncthreads();
    if (warp == 0) {     // serial greedy over (short) nonzero-row list only
        unsigned kw = keepw[lane];
        int L = Lsh;
        for (int t = 0; t < L; t++) {
            int i = list[t];
            unsigned ow = __shfl_sync(FULLM, kw, i >> 5);
            if ((ow >> (i & 31)) & 1u) kw &= ~__ldcg(&g_mask[i * 32 + lane]);
        }
        keepw[lane] = kw;
    }
    __syncthreads();
    for (int r = tid; r < KTOP; r += 256) {
        bool kp = (keepw[r >> 5] >> (r & 31)) & 1u;
        float4 b = __ldcg(&g_box[r]);
        float c = __ldcg(&g_conf[r]);
        float lf = __ldcg(&g_labf[r]);
        float* o = out + r * 6;
        if (kp) { o[0] = b.x; o[1] = b.y; o[2] = b.z; o[3] = b.w; o[4] = c; o[5] = lf; }
        else    { o[0] = 0.f; o[1] = 0.f; o[2] = 0.f; o[3] = 0.f; o[4] = 0.f; o[5] = 0.f; }
    }
    if (tid == 0) { g_done4 = 0u; g_maxc = 0u; }
}

// ---------------- launch ----------------
extern "C" void kernel_launch(void* const* d_in, const int* in_sizes, int n_in,
                              void* d_out, int out_size) {
    const float* boxes  = (const float*)d_in[0];
    const float* scores = (const float*)d_in[1];
    if (n_in >= 2 && in_sizes[0] > in_sizes[1]) { const float* t = boxes; boxes = scores; scores = t; }

    conf_kernel<<<N_ANCH / 64, 256>>>(scores);   // 4096 blocks, 8 anchors/warp
    hist_kernel<<<N_ANCH / 1024, 256>>>(1);      // 256 blocks, uint4 reads
    hist_kernel<<<N_ANCH / 1024, 256>>>(2);
    compact_kernel<<<N_ANCH / 1024, 256>>>();
    rank_kernel<<<CAP / 1024, 1024>>>(boxes);    // 4 blocks; last does prep
    mask_kernel<<<KTOP / 8, 256>>>((float*)d_out); // 128 blocks; last does final
}